// round 3
// baseline (speedup 1.0000x reference)
#include <cuda_runtime.h>
#include <math.h>

#define BATCH 8
#define M0 228000
#define M1 57000
#define KSEL 2000
#define CAND 4000
#define POSTK 1000
#define IMG_Wf 1216.0f
#define IMG_Hf 800.0f
#define LVL_OFF 1217.0f
#define SCALE_CLAMPF 4.135166556742356f
#define NMS_T 0.7f
#define CBUF (KSEL + 512)

// ---------------- scratch (device globals; no allocation allowed) ----------
__device__ int    g_idx[BATCH * CAND];
__device__ float4 g_boxes[BATCH * CAND];
__device__ float  g_scores[BATCH * CAND];

__device__ __forceinline__ unsigned fkey(float f) {
    unsigned u = __float_as_uint(f);
    return (u & 0x80000000u) ? ~u : (u | 0x80000000u);
}

// ---------------- K1: exact ORDERED top-K per (image, level) ---------------
// Radix-select the K-th key, compact all keys >= T as 64-bit composite
// (score_key << 32) | ~index, then rank-sort so g_idx holds candidates in
// descending-score / ascending-index order — bit-matching lax.top_k output
// order (which jnp.argmax tie-breaks depend on).
__global__ void topk_kernel(const float* __restrict__ lg0,
                            const float* __restrict__ lg1) {
    int blk = blockIdx.x;
    int b = blk >> 1, lvl = blk & 1;
    const float* lg = lvl ? (lg1 + (size_t)b * M1) : (lg0 + (size_t)b * M0);
    int M = lvl ? M1 : M0;
    int t = threadIdx.x;

    __shared__ unsigned hist[256];
    __shared__ unsigned sh_prefix;
    __shared__ int      sh_kRem;
    __shared__ int      sh_cnt;
    __shared__ unsigned long long ckey[CBUF];

    if (t == 0) { sh_prefix = 0u; sh_kRem = KSEL; sh_cnt = 0; }
    __syncthreads();

    // ---- 4-pass MSB radix select of the K-th largest key
    for (int shift = 24; shift >= 0; shift -= 8) {
        if (t < 256) hist[t] = 0u;
        __syncthreads();
        unsigned prefix = sh_prefix;
        unsigned pmask  = (shift == 24) ? 0u : ~((1u << (shift + 8)) - 1u);
        for (int i = t; i < M; i += 1024) {
            unsigned u = fkey(lg[i]);
            if ((u & pmask) == prefix) atomicAdd(&hist[(u >> shift) & 255u], 1u);
        }
        __syncthreads();
        if (t == 0) {
            int kr = sh_kRem, cum = 0, bsel = 0;
            for (int bin = 255; bin >= 0; --bin) {
                int c = (int)hist[bin];
                if (cum + c >= kr) { bsel = bin; sh_kRem = kr - cum; break; }
                cum += c;
            }
            sh_prefix = prefix | ((unsigned)bsel << shift);
        }
        __syncthreads();
    }
    unsigned T = sh_prefix;

    // ---- compact all keys >= T (set includes every tie at T)
    for (int i = t; i < M; i += 1024) {
        unsigned u = fkey(lg[i]);
        if (u >= T) {
            int sl = atomicAdd(&sh_cnt, 1);
            if (sl < CBUF)
                ckey[sl] = ((unsigned long long)u << 32) | (unsigned)(~i);
        }
    }
    __syncthreads();
    int n = sh_cnt < CBUF ? sh_cnt : CBUF;

    // ---- rank sort: rank = #{composite keys greater}; keep rank < KSEL
    int base = b * CAND + lvl * KSEL;
    for (int e = t; e < n; e += 1024) {
        unsigned long long k = ckey[e];
        int r = 0;
        for (int c = 0; c < n; ++c) r += (ckey[c] > k);
        if (r < KSEL) g_idx[base + r] = (int)(~(unsigned)k);
    }
}

// ---------------- K2: gather + Box2Box decode + clip -----------------------
// Strict per-op rounding (no FMA contraction) to match XLA's per-HLO rounding.
__global__ void gather_kernel(const float* __restrict__ lg0, const float* __restrict__ dl0,
                              const float* __restrict__ lg1, const float* __restrict__ dl1,
                              const float* __restrict__ an0, const float* __restrict__ an1) {
    int tid = blockIdx.x * blockDim.x + threadIdx.x;
    if (tid >= BATCH * CAND) return;
    int b = tid / CAND;
    int pos = tid - b * CAND;
    int lvl = (pos >= KSEL);
    int idx = g_idx[tid];

    const float* lg = lvl ? (lg1 + (size_t)b * M1) : (lg0 + (size_t)b * M0);
    const float* dl = lvl ? (dl1 + ((size_t)b * M1 + idx) * 4)
                          : (dl0 + ((size_t)b * M0 + idx) * 4);
    const float* an = (lvl ? an1 : an0) + (size_t)idx * 4;

    float4 a = *(const float4*)an;
    float4 d = *(const float4*)dl;
    float score = lg[idx];

    float w  = __fsub_rn(a.z, a.x);
    float h  = __fsub_rn(a.w, a.y);
    float cx = __fadd_rn(a.x, __fmul_rn(0.5f, w));
    float cy = __fadd_rn(a.y, __fmul_rn(0.5f, h));
    float dw = fminf(d.z, SCALE_CLAMPF);
    float dh = fminf(d.w, SCALE_CLAMPF);
    float pcx = __fadd_rn(__fmul_rn(d.x, w), cx);
    float pcy = __fadd_rn(__fmul_rn(d.y, h), cy);
    float pw  = __fmul_rn(expf(dw), w);
    float ph  = __fmul_rn(expf(dh), h);
    float hpw = __fmul_rn(0.5f, pw);
    float hph = __fmul_rn(0.5f, ph);
    float x1 = __fsub_rn(pcx, hpw);
    float y1 = __fsub_rn(pcy, hph);
    float x2 = __fadd_rn(pcx, hpw);
    float y2 = __fadd_rn(pcy, hph);
    x1 = fminf(fmaxf(x1, 0.f), IMG_Wf);
    x2 = fminf(fmaxf(x2, 0.f), IMG_Wf);
    y1 = fminf(fmaxf(y1, 0.f), IMG_Hf);
    y2 = fminf(fmaxf(y2, 0.f), IMG_Hf);

    g_boxes[tid] = make_float4(x1, y1, x2, y2);
    g_scores[tid] = score;
}

// ---------------- K3: greedy NMS, one block per image ----------------------
// dynamic smem layout: float4 boxS[CAND]; float4 nbS[CAND]; float areas[CAND]; float s[CAND]
#define NMS_SMEM (CAND * (16 + 16 + 4 + 4))

__global__ void nms_kernel(float* __restrict__ out) {
    int b = blockIdx.x;
    extern __shared__ float smraw[];
    float4* boxS  = (float4*)smraw;
    float4* nbS   = boxS + CAND;
    float*  areas = (float*)(nbS + CAND);
    float*  s     = areas + CAND;
    __shared__ float redV[32];
    __shared__ int   redI[32];
    __shared__ float sh_v;
    __shared__ int   sh_j;

    int t = threadIdx.x;
    int lane = t & 31, warp = t >> 5;

    for (int i = t; i < CAND; i += 1024) {
        float4 bx = g_boxes[b * CAND + i];
        float off = (i >= KSEL) ? LVL_OFF : 0.f;
        float4 nb = make_float4(__fadd_rn(bx.x, off), __fadd_rn(bx.y, off),
                                __fadd_rn(bx.z, off), __fadd_rn(bx.w, off));
        boxS[i] = bx;
        nbS[i] = nb;
        areas[i] = __fmul_rn(__fsub_rn(nb.z, nb.x), __fsub_rn(nb.w, nb.y));
        s[i] = g_scores[b * CAND + i];
    }
    __syncthreads();
    // pad candidate = array index 0 (sorted slot 0 = top level-0 score;
    // matches jnp.argmax over an all -inf score vector)
    float4 padBox   = boxS[0];
    float  padScore = s[0];

    int it = 0;
    for (; it < POSTK; ++it) {
        // ---- block argmax with (value desc, index asc) tie-break
        float bv = -INFINITY; int bi = 0x7fffffff;
        for (int i = t; i < CAND; i += 1024) {
            float v = s[i];
            if (v > bv) { bv = v; bi = i; }
        }
        for (int off = 16; off > 0; off >>= 1) {
            float ov = __shfl_down_sync(0xffffffffu, bv, off);
            int   oi = __shfl_down_sync(0xffffffffu, bi, off);
            if (ov > bv || (ov == bv && oi < bi)) { bv = ov; bi = oi; }
        }
        if (lane == 0) { redV[warp] = bv; redI[warp] = bi; }
        __syncthreads();
        if (t < 32) {
            bv = redV[t]; bi = redI[t];
            for (int off = 16; off > 0; off >>= 1) {
                float ov = __shfl_down_sync(0xffffffffu, bv, off);
                int   oi = __shfl_down_sync(0xffffffffu, bi, off);
                if (ov > bv || (ov == bv && oi < bi)) { bv = ov; bi = oi; }
            }
            if (t == 0) { sh_v = bv; sh_j = bi; }
        }
        __syncthreads();
        float jv = sh_v;
        if (jv == -INFINITY) break;   // exhausted: pad remainder below
        int j = sh_j;
        float4 jb = nbS[j];
        float  ja = areas[j];

        if (t == 0) {
            float4 ob = boxS[j];
            float* o = out + ((size_t)b * POSTK + it) * 5;
            o[0] = ob.x; o[1] = ob.y; o[2] = ob.z; o[3] = ob.w; o[4] = jv;
        }

        // ---- suppression (reference formula, strict per-op rounding)
        for (int i = t; i < CAND; i += 1024) {
            float v = s[i];
            if (v == -INFINITY) continue;
            float4 nb = nbS[i];
            float ix1 = fmaxf(jb.x, nb.x), iy1 = fmaxf(jb.y, nb.y);
            float ix2 = fminf(jb.z, nb.z), iy2 = fminf(jb.w, nb.w);
            float iw = fmaxf(__fsub_rn(ix2, ix1), 0.f);
            float ih = fmaxf(__fsub_rn(iy2, iy1), 0.f);
            float inter = __fmul_rn(iw, ih);
            float denom = fmaxf(__fsub_rn(__fadd_rn(ja, areas[i]), inter), 1e-6f);
            float iou = __fdiv_rn(inter, denom);
            if (iou > NMS_T || i == j) s[i] = -INFINITY;
        }
        __syncthreads();
    }

    // ---- pad remaining rows (reference selects index 0 with real score)
    for (int r = it + t; r < POSTK; r += 1024) {
        float* o = out + ((size_t)b * POSTK + r) * 5;
        o[0] = padBox.x; o[1] = padBox.y; o[2] = padBox.z; o[3] = padBox.w;
        o[4] = padScore;
    }
}

// ---------------------------------------------------------------------------
extern "C" void kernel_launch(void* const* d_in, const int* in_sizes, int n_in,
                              void* d_out, int out_size) {
    const float* lg0 = (const float*)d_in[0];
    const float* dl0 = (const float*)d_in[1];
    const float* lg1 = (const float*)d_in[2];
    const float* dl1 = (const float*)d_in[3];
    const float* an0 = (const float*)d_in[4];
    const float* an1 = (const float*)d_in[5];
    float* out = (float*)d_out;

    topk_kernel<<<BATCH * 2, 1024>>>(lg0, lg1);
    gather_kernel<<<(BATCH * CAND + 255) / 256, 256>>>(lg0, dl0, lg1, dl1, an0, an1);
    cudaFuncSetAttribute(nms_kernel, cudaFuncAttributeMaxDynamicSharedMemorySize, NMS_SMEM);
    nms_kernel<<<BATCH, 1024, NMS_SMEM>>>(out);
}

// round 6
// speedup vs baseline: 2.8527x; 2.8527x over previous
#include <cuda_runtime.h>
#include <math.h>

#define BATCH 8
#define M0 228000
#define M1 57000
#define KSEL 2000
#define CAND 4000
#define POSTK 1000
#define IMG_Wf 1216.0f
#define IMG_Hf 800.0f
#define LVL_OFF 1217.0f
#define SCALE_CLAMPF 4.135166556742356f
#define NMS_T 0.7f
#define NWORD 125            /* 4000/32 */
#define MROW  128            /* padded words per mask row (512B = 32 uint4) */
#define MROW4 32             /* uint4 per mask row */
#define RING  80             /* ring depth (rows) in K4 smem: 80*32*16B = 40KB */

// ---------------- scratch (device globals; no allocation allowed) ----------
__device__ int      g_cand[BATCH * CAND];      // packed (lvl<<18)|idx, SET only
__device__ float4   g_sbox[BATCH * CAND];      // sorted order, unoffset clipped
__device__ float4   g_snb [BATCH * CAND];      // sorted order, level-offset
__device__ float    g_sarea[BATCH * CAND];
__device__ float    g_sscore[BATCH * CAND];
__device__ int      g_slvl[BATCH * CAND];
__device__ uint4    g_mask4[(size_t)BATCH * CAND * MROW4];   // 16 MB, 16B-aligned

__device__ __forceinline__ unsigned fkey(float f) {
    unsigned u = __float_as_uint(f);
    return (u & 0x80000000u) ? ~u : (u | 0x80000000u);
}
__device__ __forceinline__ float fkey_inv(unsigned u) {
    return (u & 0x80000000u) ? __uint_as_float(u & 0x7fffffffu)
                             : __uint_as_float(~u);
}

// ---------------- K1: exact top-K SET per (image, level) -------------------
__global__ void topk_kernel(const float* __restrict__ lg0,
                            const float* __restrict__ lg1) {
    int blk = blockIdx.x;
    int b = blk >> 1, lvl = blk & 1;
    const float* lg = lvl ? (lg1 + (size_t)b * M1) : (lg0 + (size_t)b * M0);
    int M = lvl ? M1 : M0;
    int t = threadIdx.x;

    __shared__ unsigned hist[256];
    __shared__ unsigned sh_prefix;
    __shared__ int      sh_kRem, sh_cnt, sh_nTie;
    __shared__ int      tieBuf[512];

    if (t == 0) { sh_prefix = 0u; sh_kRem = KSEL; sh_cnt = 0; sh_nTie = 0; }
    __syncthreads();

    const float4* lg4 = (const float4*)lg;
    int M4 = M >> 2;

    // 4-pass MSB radix select of the K-th largest key (exact)
    for (int shift = 24; shift >= 0; shift -= 8) {
        if (t < 256) hist[t] = 0u;
        __syncthreads();
        unsigned prefix = sh_prefix;
        unsigned pmask  = (shift == 24) ? 0u : ~((1u << (shift + 8)) - 1u);
        for (int i = t; i < M4; i += 1024) {
            float4 v = lg4[i];
            unsigned u0 = fkey(v.x), u1 = fkey(v.y), u2 = fkey(v.z), u3 = fkey(v.w);
            if ((u0 & pmask) == prefix) atomicAdd(&hist[(u0 >> shift) & 255u], 1u);
            if ((u1 & pmask) == prefix) atomicAdd(&hist[(u1 >> shift) & 255u], 1u);
            if ((u2 & pmask) == prefix) atomicAdd(&hist[(u2 >> shift) & 255u], 1u);
            if ((u3 & pmask) == prefix) atomicAdd(&hist[(u3 >> shift) & 255u], 1u);
        }
        __syncthreads();
        if (t == 0) {
            int kr = sh_kRem, cum = 0, bsel = 0;
            for (int bin = 255; bin >= 0; --bin) {
                int c = (int)hist[bin];
                if (cum + c >= kr) { bsel = bin; sh_kRem = kr - cum; break; }
                cum += c;
            }
            sh_prefix = prefix | ((unsigned)bsel << shift);
        }
        __syncthreads();
    }
    unsigned T = sh_prefix;

    int base = b * CAND + lvl * KSEL;
    for (int i4 = t; i4 < M4; i4 += 1024) {
        float4 v = lg4[i4];
        int i = i4 * 4;
        unsigned uu[4] = { fkey(v.x), fkey(v.y), fkey(v.z), fkey(v.w) };
        #pragma unroll
        for (int c = 0; c < 4; ++c) {
            unsigned u = uu[c];
            if (u > T) {
                int sl = atomicAdd(&sh_cnt, 1);
                g_cand[base + sl] = (lvl << 18) | (i + c);
            } else if (u == T) {
                int sl = atomicAdd(&sh_nTie, 1);
                if (sl < 512) tieBuf[sl] = i + c;
            }
        }
    }
    __syncthreads();
    if (t == 0) {
        int n = sh_nTie < 512 ? sh_nTie : 512;
        int need = KSEL - sh_cnt;
        for (int a = 0; a < need && a < n; ++a) {
            int best = a;
            for (int c = a + 1; c < n; ++c)
                if (tieBuf[c] < tieBuf[best]) best = c;
            int tmp = tieBuf[a]; tieBuf[a] = tieBuf[best]; tieBuf[best] = tmp;
            g_cand[base + sh_cnt + a] = (lvl << 18) | tieBuf[a];
        }
    }
}

// ---------------- K2: per-image sort + decode ------------------------------
__global__ void sortdecode_kernel(const float* __restrict__ lg0, const float* __restrict__ dl0,
                                  const float* __restrict__ lg1, const float* __restrict__ dl1,
                                  const float* __restrict__ an0, const float* __restrict__ an1) {
    int b = blockIdx.x, t = threadIdx.x;
    __shared__ unsigned long long key[4096];

    for (int i = t; i < 4096; i += 1024) {
        if (i < CAND) {
            int p = g_cand[b * CAND + i];
            int lvl = p >> 18, idx = p & 0x3ffff;
            float sc = lvl ? lg1[(size_t)b * M1 + idx] : lg0[(size_t)b * M0 + idx];
            key[i] = ((unsigned long long)fkey(sc) << 32) | (unsigned)(~(unsigned)p);
        } else key[i] = 0ull;
    }
    __syncthreads();

    // bitonic sort, descending: (score desc, lvl asc, idx asc) = concat order
    for (int k = 2; k <= 4096; k <<= 1) {
        for (int j = k >> 1; j > 0; j >>= 1) {
            for (int e = t; e < 4096; e += 1024) {
                int ix = e ^ j;
                if (ix > e) {
                    unsigned long long a = key[e], bb = key[ix];
                    bool swp = ((e & k) == 0) ? (a < bb) : (a > bb);
                    if (swp) { key[e] = bb; key[ix] = a; }
                }
            }
            __syncthreads();
        }
    }

    // decode boxes in sorted order (strict per-op rounding, matches XLA)
    for (int i = t; i < CAND; i += 1024) {
        unsigned long long k = key[i];
        unsigned p = ~((unsigned)k);
        int lvl = (int)(p >> 18), idx = (int)(p & 0x3ffffu);
        float score = fkey_inv((unsigned)(k >> 32));

        const float* dl = lvl ? (dl1 + ((size_t)b * M1 + idx) * 4)
                              : (dl0 + ((size_t)b * M0 + idx) * 4);
        const float* an = (lvl ? an1 : an0) + (size_t)idx * 4;
        float4 a = *(const float4*)an;
        float4 d = *(const float4*)dl;

        float w  = __fsub_rn(a.z, a.x);
        float h  = __fsub_rn(a.w, a.y);
        float cx = __fadd_rn(a.x, __fmul_rn(0.5f, w));
        float cy = __fadd_rn(a.y, __fmul_rn(0.5f, h));
        float dw = fminf(d.z, SCALE_CLAMPF);
        float dh = fminf(d.w, SCALE_CLAMPF);
        float pcx = __fadd_rn(__fmul_rn(d.x, w), cx);
        float pcy = __fadd_rn(__fmul_rn(d.y, h), cy);
        float pw  = __fmul_rn(expf(dw), w);
        float ph  = __fmul_rn(expf(dh), h);
        float hpw = __fmul_rn(0.5f, pw);
        float hph = __fmul_rn(0.5f, ph);
        float x1 = __fsub_rn(pcx, hpw);
        float y1 = __fsub_rn(pcy, hph);
        float x2 = __fadd_rn(pcx, hpw);
        float y2 = __fadd_rn(pcy, hph);
        x1 = fminf(fmaxf(x1, 0.f), IMG_Wf);
        x2 = fminf(fmaxf(x2, 0.f), IMG_Wf);
        y1 = fminf(fmaxf(y1, 0.f), IMG_Hf);
        y2 = fminf(fmaxf(y2, 0.f), IMG_Hf);

        int gi = b * CAND + i;
        g_sbox[gi] = make_float4(x1, y1, x2, y2);
        float off = lvl ? LVL_OFF : 0.f;
        float nx1 = __fadd_rn(x1, off), ny1 = __fadd_rn(y1, off);
        float nx2 = __fadd_rn(x2, off), ny2 = __fadd_rn(y2, off);
        g_snb[gi]   = make_float4(nx1, ny1, nx2, ny2);
        g_sarea[gi] = __fmul_rn(__fsub_rn(nx2, nx1), __fsub_rn(ny2, ny1));
        g_sscore[gi] = score;
        g_slvl[gi]  = lvl;
    }
}

// ---------------- K3: 4000x4000 suppression bitmask per image --------------
__global__ void mask_kernel() {
    int blk = blockIdx.x;
    int b = blk / 250, rg = blk % 250;
    int t = threadIdx.x, wi = t >> 5, lane = t & 31;
    unsigned* gm = (unsigned*)g_mask4;

    for (int rr = 0; rr < 2; ++rr) {
        int row = rg * 16 + wi * 2 + rr;
        int gr = b * CAND + row;
        float4 jb = g_snb[gr];
        float  ja = g_sarea[gr];
        unsigned* mrow = gm + (size_t)gr * MROW;
        for (int w = 0; w < NWORD; ++w) {
            int col = b * CAND + w * 32 + lane;
            float4 nb = g_snb[col];
            float  na = g_sarea[col];
            float ix1 = fmaxf(jb.x, nb.x), iy1 = fmaxf(jb.y, nb.y);
            float ix2 = fminf(jb.z, nb.z), iy2 = fminf(jb.w, nb.w);
            float iw = fmaxf(__fsub_rn(ix2, ix1), 0.f);
            float ih = fmaxf(__fsub_rn(iy2, iy1), 0.f);
            float inter = __fmul_rn(iw, ih);
            float denom = fmaxf(__fsub_rn(__fadd_rn(ja, na), inter), 1e-6f);
            float iou = __fdiv_rn(inter, denom);
            unsigned bits = __ballot_sync(0xffffffffu, iou > NMS_T);
            if (lane == 0) mrow[w] = bits;
        }
    }
}

// ---------------- K4: serial sorted scan, 2 warps per image ----------------
__global__ void scan_kernel(float* __restrict__ out) {
    int b = blockIdx.x;
    int t = threadIdx.x, warp = t >> 5, lane = t & 31;
    __shared__ volatile int sh_prog, sh_cons, sh_done;
    __shared__ uint4 ring[RING * MROW4];    // 40 KB: 32 uint4 (128 words) per row

    if (t == 0) { sh_prog = 0; sh_cons = 0; sh_done = 0; }
    __syncthreads();

    const uint4* mbase = g_mask4 + (size_t)b * CAND * MROW4;

    if (warp == 1) {
        // -------- producer: stream mask rows into the ring --------
        for (int r = 0; r < CAND; ++r) {
            if ((r & 7) == 0) {
                int stop = 0;
                if (lane == 0) {
                    // gate with 8-row margin: batch-of-8 can overrun by <=7
                    while (r >= sh_cons + (RING - 8)) { if (sh_done) break; }
                    if (sh_done) stop = 1;
                }
                stop = __shfl_sync(0xffffffffu, stop, 0);
                if (stop) break;
            }
            // 32 lanes x 1 uint4 = full 128-word row
            ring[(r % RING) * MROW4 + lane] = mbase[(size_t)r * MROW4 + lane];
            if ((r & 7) == 7 || r == CAND - 1) {
                __threadfence_block();
                __syncwarp();
                if (lane == 0) sh_prog = r + 1;
            }
        }
    } else if (warp == 0) {
        // -------- consumer: register-resident 4000-bit suppressed mask ------
        unsigned m0 = 0, m1 = 0, m2 = 0, m3 = 0;   // lane L owns words 4L..4L+3

        // pad candidate = concat position 0 = first lvl-0 entry in sorted order
        int padi = 0;
        if (lane == 0) { while (g_slvl[b * CAND + padi] != 0) ++padi; }
        padi = __shfl_sync(0xffffffffu, padi, 0);
        float4 padBox  = g_sbox[b * CAND + padi];
        float padScore = g_sscore[b * CAND + padi];

        int sel = 0;
        for (int w = 0; w < NWORD && sel < POSTK; ++w) {
            if (lane == 0) sh_cons = w * 32;
            unsigned v = (w & 3) == 0 ? m0 : (w & 3) == 1 ? m1 : (w & 3) == 2 ? m2 : m3;
            unsigned cur = __shfl_sync(0xffffffffu, v, w >> 2);
            unsigned alive = ~cur;
            while (alive && sel < POSTK) {
                int bit = __ffs(alive) - 1;
                int i = w * 32 + bit;
                if (lane == 0) { while (sh_prog < i + 1) {} }
                __syncwarp();
                const volatile unsigned* rr =
                    (const volatile unsigned*)(ring + (i % RING) * MROW4) + lane * 4;
                m0 |= rr[0]; m1 |= rr[1]; m2 |= rr[2]; m3 |= rr[3];
                if (lane == 0) {
                    float4 bx = g_sbox[b * CAND + i];
                    float scv = g_sscore[b * CAND + i];
                    float* o = out + ((size_t)b * POSTK + sel) * 5;
                    o[0] = bx.x; o[1] = bx.y; o[2] = bx.z; o[3] = bx.w; o[4] = scv;
                }
                sel++;
                unsigned v2 = (w & 3) == 0 ? m0 : (w & 3) == 1 ? m1 : (w & 3) == 2 ? m2 : m3;
                unsigned curw = __shfl_sync(0xffffffffu, v2, w >> 2);
                alive &= ~curw;
                alive &= ~(1u << bit);
            }
        }
        if (lane == 0) sh_done = 1;
        __threadfence_block();

        // pad remaining rows
        for (int r = sel + lane; r < POSTK; r += 32) {
            float* o = out + ((size_t)b * POSTK + r) * 5;
            o[0] = padBox.x; o[1] = padBox.y; o[2] = padBox.z; o[3] = padBox.w;
            o[4] = padScore;
        }
    }
}

// ---------------------------------------------------------------------------
extern "C" void kernel_launch(void* const* d_in, const int* in_sizes, int n_in,
                              void* d_out, int out_size) {
    const float* lg0 = (const float*)d_in[0];
    const float* dl0 = (const float*)d_in[1];
    const float* lg1 = (const float*)d_in[2];
    const float* dl1 = (const float*)d_in[3];
    const float* an0 = (const float*)d_in[4];
    const float* an1 = (const float*)d_in[5];
    float* out = (float*)d_out;

    topk_kernel<<<BATCH * 2, 1024>>>(lg0, lg1);
    sortdecode_kernel<<<BATCH, 1024>>>(lg0, dl0, lg1, dl1, an0, an1);
    mask_kernel<<<BATCH * 250, 256>>>();
    scan_kernel<<<BATCH, 64>>>(out);
}